// round 2
// baseline (speedup 1.0000x reference)
#include <cuda_runtime.h>
#include <cstdint>

#define MAX_SPIKE_TIME 100000.0f

// Problem constants (from reference setup_inputs)
static constexpr int B_SIZE   = 64;
static constexpr int IN_SIZE  = 1024;
static constexpr int NP1      = IN_SIZE + 1;   // 1025 (with appended 1.0)
static constexpr int OUT_SIZE = 512;
static constexpr int NSORT    = 2048;          // next pow2 >= 1025
static constexpr int THREADS  = 256;           // threads per block
static constexpr int J_PER_BLOCK = 256;        // outputs per block (2 blocks per batch)

__global__ __launch_bounds__(THREADS, 2)
void snn_layer_kernel(const float* __restrict__ layer_in,
                      const float* __restrict__ weight,
                      const float* __restrict__ delay,
                      float* __restrict__ out)
{
    __shared__ unsigned long long sbuf[NSORT];     // 16 KB sort buffer
    __shared__ float2 xi[NP1 + 1];                 // (sorted value, idx-bits), +1 sentinel

    const int tid = threadIdx.x;
    const int b   = blockIdx.x >> 1;               // batch row
    const int j   = ((blockIdx.x & 1) * J_PER_BLOCK) + tid;  // output column

    // ---- Phase 1: build keys  key = (float_bits(x) << 32) | index ----
    // x >= 0 so float-bit ordering == value ordering; low index bits give the
    // same stable tie-break as jnp.argsort.
    const float* lin = layer_in + (size_t)b * IN_SIZE;
    for (int i = tid; i < NSORT; i += THREADS) {
        unsigned long long key;
        if (i < IN_SIZE) {
            float d  = delay[i];
            float xv = lin[i] * expf(fmaxf(d, 0.0f));   // accurate exp, matches jnp
            key = ((unsigned long long)__float_as_uint(xv) << 32) | (unsigned)i;
        } else if (i == IN_SIZE) {
            key = ((unsigned long long)__float_as_uint(1.0f) << 32) | (unsigned)i;
        } else {
            key = ~0ull;  // padding, sorts to the end
        }
        sbuf[i] = key;
    }
    __syncthreads();

    // ---- Phase 2: bitonic sort (ascending) on 2048 uint64 keys ----
    for (int k = 2; k <= NSORT; k <<= 1) {
        for (int jj = k >> 1; jj > 0; jj >>= 1) {
            for (int i = tid; i < NSORT; i += THREADS) {
                int ixj = i ^ jj;
                if (ixj > i) {
                    unsigned long long a = sbuf[i];
                    unsigned long long c = sbuf[ixj];
                    bool up = ((i & k) == 0);
                    if ((a > c) == up) { sbuf[i] = c; sbuf[ixj] = a; }
                }
            }
            __syncthreads();
        }
    }

    // ---- Phase 3: unpack into (value, index) pairs + sentinel ----
    for (int i = tid; i < NP1; i += THREADS) {
        unsigned long long key = sbuf[i];
        xi[i] = make_float2(__uint_as_float((unsigned)(key >> 32)),
                            __uint_as_float((unsigned)(key & 0xffffffffu)));
    }
    if (tid == 0) xi[NP1] = make_float2(MAX_SPIKE_TIME, 0.0f);
    __syncthreads();

    // ---- Phase 4: scan over sorted order; validity-gated running min ----
    // w_cum, wi_cum accumulate in exactly the reference's (sorted) order.
    float w_cum  = 0.0f;
    float wi_cum = 0.0f;
    float best   = MAX_SPIKE_TIME;
    float2 cur = xi[0];

    const float* Wj = weight + j;   // column j, row stride OUT_SIZE

    #pragma unroll 4
    for (int k = 0; k < NP1; ++k) {
        float2 nxt = xi[k + 1];                       // broadcast LDS.64
        int row = (int)__float_as_uint(cur.y);        // original input index
        float w = __ldg(Wj + (size_t)row * OUT_SIZE); // coalesced across lanes

        // mirror reference: ws*xs (unfused) then cumsum
        wi_cum = __fadd_rn(wi_cum, __fmul_rn(w, cur.x));
        w_cum  = __fadd_rn(w_cum, w);

        float denom = fmaxf(w_cum - 1.0f, 1e-10f);
        float cand  = wi_cum / denom;                 // exact IEEE division

        // reference gating:
        //   w_cum < 1         -> MAX
        //   cand  < xs[k]     -> MAX
        //   cand  > xs[k+1]   -> MAX
        bool valid = (w_cum >= 1.0f) & (cand >= cur.x) & (cand <= nxt.x);
        if (valid) best = fminf(best, cand);

        cur = nxt;
    }

    out[(size_t)b * OUT_SIZE + j] = best;
}

extern "C" void kernel_launch(void* const* d_in, const int* in_sizes, int n_in,
                              void* d_out, int out_size)
{
    const float* layer_in = (const float*)d_in[0];  // (64, 1024)
    const float* weight   = (const float*)d_in[1];  // (1025, 512)
    const float* delay    = (const float*)d_in[2];  // (1024,)
    float* out = (float*)d_out;                     // (64, 512)

    dim3 grid(B_SIZE * (OUT_SIZE / J_PER_BLOCK));   // 128 blocks
    dim3 block(THREADS);                            // 256 threads
    snn_layer_kernel<<<grid, block>>>(layer_in, weight, delay, out);
}

// round 6
// speedup vs baseline: 2.5174x; 2.5174x over previous
#include <cuda_runtime.h>
#include <cstdint>

#define MAX_SPIKE_TIME 100000.0f

// Problem constants (from reference setup_inputs)
static constexpr int B_SIZE   = 64;
static constexpr int IN_SIZE  = 1024;
static constexpr int NP1      = IN_SIZE + 1;   // 1025 (with appended 1.0)
static constexpr int OUT_SIZE = 512;
static constexpr int NSORT    = 1024;          // sort only the 1024 real inputs
static constexpr int THREADS  = 256;
static constexpr int J_PER_BLOCK = 256;        // outputs per block (2 blocks per batch)
static constexpr int PF       = 8;             // prefetch depth (reg ring buffer)
static constexpr int XI_SIZE  = NP1 + PF + 1;  // sorted array + sentinel/pad for prefetch

__global__ __launch_bounds__(THREADS, 2)
void snn_layer_kernel(const float* __restrict__ layer_in,
                      const float* __restrict__ weight,
                      const float* __restrict__ delay,
                      float* __restrict__ out)
{
    __shared__ unsigned long long sbuf[NSORT];  // 8 KB sort buffer
    __shared__ float2 xi[XI_SIZE];              // (sorted value, idx-bits) + pad
    __shared__ int s_pos;                       // insertion position of appended 1.0

    const int tid = threadIdx.x;
    const int b   = blockIdx.x >> 1;
    const int j   = ((blockIdx.x & 1) * J_PER_BLOCK) + tid;

    if (tid == 0) s_pos = 0;
    __syncthreads();

    // ---- Phase 1: build keys  key = (float_bits(x) << 32) | index ----
    // x >= 0 so float-bit order == value order; low index bits reproduce
    // jnp.argsort's stable tie-break. Also count elements <= 1.0 to find the
    // stable insertion position of the appended (1.0, idx=1024) element:
    // its index is larger than all others, so it goes after every x <= 1.0.
    const float* lin = layer_in + (size_t)b * IN_SIZE;
    int cnt = 0;
    for (int i = tid; i < NSORT; i += THREADS) {
        float d  = delay[i];
        float xv = lin[i] * expf(fmaxf(d, 0.0f));   // accurate exp, matches jnp
        cnt += (xv <= 1.0f);
        sbuf[i] = ((unsigned long long)__float_as_uint(xv) << 32) | (unsigned)i;
    }
    if (cnt) atomicAdd(&s_pos, cnt);
    __syncthreads();

    // ---- Phase 2: bitonic sort (ascending) on 1024 uint64 keys ----
    for (int k = 2; k <= NSORT; k <<= 1) {
        for (int jj = k >> 1; jj > 0; jj >>= 1) {
            for (int i = tid; i < NSORT; i += THREADS) {
                int ixj = i ^ jj;
                if (ixj > i) {
                    unsigned long long a = sbuf[i];
                    unsigned long long c = sbuf[ixj];
                    bool up = ((i & k) == 0);
                    if ((a > c) == up) { sbuf[i] = c; sbuf[ixj] = a; }
                }
            }
            __syncthreads();
        }
    }

    // ---- Phase 3: unpack with insertion of (1.0, idx=1024) + pad ----
    const int pos = s_pos;
    for (int p = tid; p < NSORT; p += THREADS) {
        unsigned long long key = sbuf[p];
        int dest = p + (p >= pos);
        xi[dest] = make_float2(__uint_as_float((unsigned)(key >> 32)),
                               __uint_as_float((unsigned)(key & 0xffffffffu)));
    }
    if (tid == 0) xi[pos] = make_float2(1.0f, __uint_as_float(1024u));
    // pad [NP1 .. XI_SIZE): sentinel + prefetch overrun (row 0 is safe to read)
    if (NP1 + tid < XI_SIZE) xi[NP1 + tid] = make_float2(MAX_SPIKE_TIME, 0.0f);
    __syncthreads();

    // ---- Phase 4: scan with explicit PF-deep prefetch pipeline ----
    float w_cum  = 0.0f;
    float wi_cum = 0.0f;
    float best   = MAX_SPIKE_TIME;
    const float* Wj = weight + j;

    // preload PF weights (independent LDGs, all in flight together)
    float wbuf[PF];
    #pragma unroll
    for (int p = 0; p < PF; ++p) {
        int row = (int)__float_as_uint(xi[p].y);
        wbuf[p] = __ldg(Wj + (size_t)row * OUT_SIZE);
    }

    float2 cur = xi[0];

    #pragma unroll 1
    for (int kb = 0; kb < IN_SIZE; kb += PF) {    // 1024 = 128 groups of 8
        #pragma unroll
        for (int u = 0; u < PF; ++u) {
            const int k = kb + u;
            float2 nxt = xi[k + 1];               // broadcast LDS.64
            float  w   = wbuf[u];
            // refill slot: issue LDG for iteration k+PF (consumed ~8 iters later)
            int prow = (int)__float_as_uint(xi[k + PF].y);
            wbuf[u] = __ldg(Wj + (size_t)prow * OUT_SIZE);

            // mirror reference: ws*xs (unfused) then cumsum
            wi_cum = __fadd_rn(wi_cum, __fmul_rn(w, cur.x));
            w_cum  = __fadd_rn(w_cum, w);

            float denom = fmaxf(w_cum - 1.0f, 1e-10f);
            float cand  = wi_cum / denom;         // exact IEEE division

            bool valid = (w_cum >= 1.0f) & (cand >= cur.x) & (cand <= nxt.x);
            if (valid) best = fminf(best, cand);

            cur = nxt;
        }
    }

    // epilogue: k = 1024 (wbuf[0] was refilled with row(xi[1024]) at kb=1016)
    {
        float2 nxt = xi[NP1];                     // MAX sentinel
        float  w   = wbuf[0];
        wi_cum = __fadd_rn(wi_cum, __fmul_rn(w, cur.x));
        w_cum  = __fadd_rn(w_cum, w);
        float denom = fmaxf(w_cum - 1.0f, 1e-10f);
        float cand  = wi_cum / denom;
        bool valid = (w_cum >= 1.0f) & (cand >= cur.x) & (cand <= nxt.x);
        if (valid) best = fminf(best, cand);
    }

    out[(size_t)b * OUT_SIZE + j] = best;
}

extern "C" void kernel_launch(void* const* d_in, const int* in_sizes, int n_in,
                              void* d_out, int out_size)
{
    const float* layer_in = (const float*)d_in[0];  // (64, 1024)
    const float* weight   = (const float*)d_in[1];  // (1025, 512)
    const float* delay    = (const float*)d_in[2];  // (1024,)
    float* out = (float*)d_out;                     // (64, 512)

    dim3 grid(B_SIZE * (OUT_SIZE / J_PER_BLOCK));   // 128 blocks
    dim3 block(THREADS);                            // 256 threads
    snn_layer_kernel<<<grid, block>>>(layer_in, weight, delay, out);
}

// round 7
// speedup vs baseline: 4.7782x; 1.8981x over previous
#include <cuda_runtime.h>
#include <cstdint>

#define MAX_SPIKE_TIME 100000.0f

// Problem constants (from reference setup_inputs)
static constexpr int B_SIZE   = 64;
static constexpr int IN_SIZE  = 1024;
static constexpr int NP1      = IN_SIZE + 1;   // 1025 (with appended 1.0)
static constexpr int OUT_SIZE = 512;
static constexpr int NSORT    = 1024;          // sort only the 1024 real inputs
static constexpr int THREADS  = 256;
static constexpr int J_PER_BLOCK = 256;        // outputs per block (2 blocks per batch)
static constexpr int PF       = 8;             // prefetch depth (reg ring buffer)
static constexpr int XI_SIZE  = NP1 + PF + 1;  // sorted array + sentinel/pad for prefetch

__global__ __launch_bounds__(THREADS, 2)
void snn_layer_kernel(const float* __restrict__ layer_in,
                      const float* __restrict__ weight,
                      const float* __restrict__ delay,
                      float* __restrict__ out)
{
    __shared__ unsigned long long sbuf[NSORT];  // 8 KB sort buffer
    __shared__ float2 xi[XI_SIZE];              // (sorted value, byte-offset bits) + pad
    __shared__ int s_pos;                       // insertion position of appended 1.0

    const int tid = threadIdx.x;
    const int b   = blockIdx.x >> 1;
    const int j   = ((blockIdx.x & 1) * J_PER_BLOCK) + tid;

    if (tid == 0) s_pos = 0;
    __syncthreads();

    // ---- Phase 1: build keys  key = (float_bits(x) << 32) | (index << 11) ----
    // x >= 0 so float-bit order == value order; (index<<11) is monotonic in
    // index, so low bits reproduce jnp.argsort's stable tie-break AND directly
    // encode the weight-row byte offset (row * 512 cols * 4 B = row << 11).
    // Count elements <= 1.0 to find the stable insertion position of the
    // appended (1.0, idx=1024): its index exceeds all others, so it lands
    // after every x <= 1.0.
    const float* lin = layer_in + (size_t)b * IN_SIZE;
    int cnt = 0;
    for (int i = tid; i < NSORT; i += THREADS) {
        float d  = delay[i];
        float xv = lin[i] * expf(fmaxf(d, 0.0f));   // accurate exp, matches jnp
        cnt += (xv <= 1.0f);
        sbuf[i] = ((unsigned long long)__float_as_uint(xv) << 32)
                | (unsigned)(i << 11);
    }
    if (cnt) atomicAdd(&s_pos, cnt);
    __syncthreads();

    // ---- Phase 2: bitonic sort (ascending) on 1024 uint64 keys ----
    for (int k = 2; k <= NSORT; k <<= 1) {
        for (int jj = k >> 1; jj > 0; jj >>= 1) {
            for (int i = tid; i < NSORT; i += THREADS) {
                int ixj = i ^ jj;
                if (ixj > i) {
                    unsigned long long a = sbuf[i];
                    unsigned long long c = sbuf[ixj];
                    bool up = ((i & k) == 0);
                    if ((a > c) == up) { sbuf[i] = c; sbuf[ixj] = a; }
                }
            }
            __syncthreads();
        }
    }

    // ---- Phase 3: unpack with insertion of (1.0, idx=1024) + pad ----
    const int pos = s_pos;
    for (int p = tid; p < NSORT; p += THREADS) {
        unsigned long long key = sbuf[p];
        int dest = p + (p >= pos);
        xi[dest] = make_float2(__uint_as_float((unsigned)(key >> 32)),
                               __uint_as_float((unsigned)(key & 0xffffffffu)));
    }
    if (tid == 0) xi[pos] = make_float2(1.0f, __uint_as_float(1024u << 11));
    // pad [NP1 .. XI_SIZE): sentinel + prefetch overrun (offset 0 = row 0, safe)
    if (NP1 + tid < XI_SIZE) xi[NP1 + tid] = make_float2(MAX_SPIKE_TIME, 0.0f);
    __syncthreads();

    // ---- Phase 4: division-free scan with PF-deep prefetch pipeline ----
    // All quotient comparisons are done by cross-multiplication (denom > 0);
    // the single exact IEEE division happens once at the end.
    float w_cum  = 0.0f;
    float wi_cum = 0.0f;
    float best_num = MAX_SPIKE_TIME;   // best = best_num / best_den
    float best_den = 1.0f;
    const char* Wj = (const char*)(weight + j);

    // preload PF weights (independent LDGs, all in flight together)
    float wbuf[PF];
    #pragma unroll
    for (int p = 0; p < PF; ++p) {
        unsigned off = __float_as_uint(xi[p].y);
        wbuf[p] = __ldg((const float*)(Wj + off));
    }

    float2 cur = xi[0];

    #pragma unroll 1
    for (int kb = 0; kb < IN_SIZE; kb += PF) {    // 1024 = 128 groups of 8
        #pragma unroll
        for (int u = 0; u < PF; ++u) {
            const int k = kb + u;
            float2 nxt = xi[k + 1];               // broadcast LDS.64
            float  w   = wbuf[u];
            // refill slot: issue LDG for iteration k+PF (consumed ~8 iters later)
            unsigned poff = __float_as_uint(xi[k + PF].y);
            wbuf[u] = __ldg((const float*)(Wj + poff));

            // mirror reference: ws*xs (unfused) then cumsum
            wi_cum = __fadd_rn(wi_cum, __fmul_rn(w, cur.x));
            w_cum  = __fadd_rn(w_cum, w);

            float denom = fmaxf(w_cum - 1.0f, 1e-10f);   // > 0 always

            // gates (cross-multiplied; denom > 0):
            //   cand >= xs[k]   <=> wi_cum >= xs[k]*denom
            //   cand <= xs[k+1] <=> wi_cum <= xs[k+1]*denom
            bool valid = (w_cum >= 1.0f)
                       & (wi_cum >= __fmul_rn(cur.x, denom))
                       & (wi_cum <= __fmul_rn(nxt.x, denom));
            // fraction min: wi_cum/denom < best_num/best_den
            bool better = valid
                        & (__fmul_rn(wi_cum, best_den) < __fmul_rn(best_num, denom));
            if (better) { best_num = wi_cum; best_den = denom; }

            cur = nxt;
        }
    }

    // epilogue: k = 1024 (wbuf[0] was refilled with row(xi[1024]) at kb=1016)
    {
        float2 nxt = xi[NP1];                     // MAX sentinel
        float  w   = wbuf[0];
        wi_cum = __fadd_rn(wi_cum, __fmul_rn(w, cur.x));
        w_cum  = __fadd_rn(w_cum, w);
        float denom = fmaxf(w_cum - 1.0f, 1e-10f);
        bool valid = (w_cum >= 1.0f)
                   & (wi_cum >= __fmul_rn(cur.x, denom))
                   & (wi_cum <= __fmul_rn(nxt.x, denom));
        bool better = valid
                    & (__fmul_rn(wi_cum, best_den) < __fmul_rn(best_num, denom));
        if (better) { best_num = wi_cum; best_den = denom; }
    }

    out[(size_t)b * OUT_SIZE + j] = best_num / best_den;   // one exact division
}

extern "C" void kernel_launch(void* const* d_in, const int* in_sizes, int n_in,
                              void* d_out, int out_size)
{
    const float* layer_in = (const float*)d_in[0];  // (64, 1024)
    const float* weight   = (const float*)d_in[1];  // (1025, 512)
    const float* delay    = (const float*)d_in[2];  // (1024,)
    float* out = (float*)d_out;                     // (64, 512)

    dim3 grid(B_SIZE * (OUT_SIZE / J_PER_BLOCK));   // 128 blocks
    dim3 block(THREADS);                            // 256 threads
    snn_layer_kernel<<<grid, block>>>(layer_in, weight, delay, out);
}